// round 5
// baseline (speedup 1.0000x reference)
#include <cuda_runtime.h>

// GMM score, d=1, two-phase, hybrid MUFU/FMA exponential.
//   sigma2(t) = (exp(2 t ln25) - 1) / (2 ln25)
//   e_ij = 2^( (k*tr + c1)*tr + c0 ),  k = -1/(2 ln2 sigma2)
//   out[j] = (num/den - x[j]) / sigma2[j]   (0/den guard as reference)
//
// Phase A: units of (32 queries x 1024 train elems), CHUNKS=16 chunks,
// statically interleaved over all SMs (8 warps/CTA = 2/SMSP).
// Inner loop blocks of 16 pairs: 13 via MUFU ex2 (16 cyc/pair MUFU),
// 3 via FMA-pipe exp2 (magic-round + IMAD scale + deg-5 f32x2 Horner).
// Balances MUFU ~13 cyc/pair against FMA ~12.9 cyc/pair (was MUFU-bound 16).
// Phase B: 4-way split reduction of 16 partials/query + epilogue (L2-resident).

#define TPB_A   256
#define WPB     (TPB_A / 32)
#define CHUNKS  16
#define MAXB    16384
#define RED_SUB 4

typedef unsigned long long u64;

__device__ float2 g_part[CHUNKS * MAXB];   // (num, den) partials, 2 MB

#define PACK2(d, lo, hi) \
    asm("mov.b64 %0, {%1, %2};" : "=l"(d) : "f"(lo), "f"(hi))
#define UNPACK2(lo, hi, s) \
    asm("mov.b64 {%0, %1}, %2;" : "=f"(lo), "=f"(hi) : "l"(s))
#define FMA2(d, a, b, c) \
    asm("fma.rn.f32x2 %0, %1, %2, %3;" : "=l"(d) : "l"(a), "l"(b), "l"(c))
#define ADD2(d, a, b) \
    asm("add.rn.f32x2 %0, %1, %2;" : "=l"(d) : "l"(a), "l"(b))
#define MUL2(d, a, b) \
    asm("mul.rn.f32x2 %0, %1, %2;" : "=l"(d) : "l"(a), "l"(b))
#define EX2(d, a) \
    asm("ex2.approx.ftz.f32 %0, %1;" : "=f"(d) : "f"(a))

__device__ __forceinline__ float sigma2_of(float tv) {
    const float LOG_S = 3.2188758248682006f;   // ln 25
    return (expf(2.0f * tv * LOG_S) - 1.0f) / (2.0f * LOG_S);
}

// MUFU path: 4 packed FMA-pipe ops + 2 MUFU per pair
__device__ __forceinline__ void pair_mufu(float2 v, u64 KK, u64 C1c, u64 C0c,
                                          u64& num2, u64& den2)
{
    u64 P, t1, a2, E;
    PACK2(P, v.x, v.y);
    FMA2(t1, KK, P, C1c);
    FMA2(a2, t1, P, C0c);
    float al, ah, e0, e1;
    UNPACK2(al, ah, a2);
    EX2(e0, al);
    EX2(e1, ah);
    PACK2(E, e0, e1);
    FMA2(num2, E, P, num2);
    ADD2(den2, den2, E);
}

// FMA-pipe path: exp2 via magic round + IMAD exponent assembly + deg-5 poly
__device__ __forceinline__ void pair_poly(float2 v, u64 KK, u64 C1c, u64 C0c,
                                          u64 MG2, u64 P5, u64 P4, u64 P3,
                                          u64 P2, u64 P1, u64 P0,
                                          u64& num2, u64& den2)
{
    const float MAGIC = 12582912.0f;           // 1.5 * 2^23
    u64 P, t1, a2;
    PACK2(P, v.x, v.y);
    FMA2(t1, KK, P, C1c);
    FMA2(a2, t1, P, C0c);
    float a0, a1;
    UNPACK2(a0, a1, a2);
    a0 = fmaxf(a0, -126.0f);                   // FMNMX (alu pipe)
    a1 = fmaxf(a1, -126.0f);
    u64 AC, R2;
    PACK2(AC, a0, a1);
    ADD2(R2, AC, MG2);                         // r = a + MAGIC (round to int)
    float r0, r1;
    UNPACK2(r0, r1, R2);
    float n0 = r0 - MAGIC;                     // exact
    float n1 = r1 - MAGIC;
    float f0 = a0 - n0;                        // f in [-0.5, 0.5]
    float f1 = a1 - n1;
    // s = 2^n : one IMAD per element
    unsigned s0 = __float_as_uint(r0) * 0x800000u + 0x3F800000u;
    unsigned s1 = __float_as_uint(r1) * 0x800000u + 0x3F800000u;
    u64 F, pp, S, E;
    PACK2(F, f0, f1);
    FMA2(pp, P5, F, P4);                       // deg-5 Horner for 2^f
    FMA2(pp, pp, F, P3);
    FMA2(pp, pp, F, P2);
    FMA2(pp, pp, F, P1);
    FMA2(pp, pp, F, P0);
    PACK2(S, __uint_as_float(s0), __uint_as_float(s1));
    MUL2(E, pp, S);
    FMA2(num2, E, P, num2);
    ADD2(den2, den2, E);
}

__global__ __launch_bounds__(TPB_A, 1)
void gmm_partial_kernel(const float* __restrict__ x,
                        const float* __restrict__ t,
                        const float* __restrict__ train,
                        int B, int N, int PL /* pairs per chunk, %16==0 */)
{
    extern __shared__ float2 sp[];   // CHUNKS*PL train pairs (padded)

    const int tot = CHUNKS * PL;
    for (int i = threadIdx.x; i < tot; i += TPB_A) {
        int e0 = 2 * i, e1 = 2 * i + 1;
        float a = (e0 < N) ? train[e0] : -1e30f;   // pad -> e ~ 0 on both paths
        float b = (e1 < N) ? train[e1] : -1e30f;
        sp[i] = make_float2(a, b);
    }
    __syncthreads();

    const int lane   = threadIdx.x & 31;
    const int wid    = threadIdx.x >> 5;
    const int wgid   = blockIdx.x * WPB + wid;
    const int nwarps = gridDim.x * WPB;

    const int qwarps = (B + 31) >> 5;
    const int units  = qwarps * CHUNKS;

    const float INV_LN2 = 1.4426950408889634f;
    const float MAGIC   = 12582912.0f;

    // packed constants
    u64 MG2, P5, P4, P3, P2, P0c, P1c;
    PACK2(MG2, MAGIC, MAGIC);
    {
        const float c5 = 0.0013333558f, c4 = 0.0096181291f, c3 = 0.0555041087f,
                    c2 = 0.2402265070f, c1p = 0.6931471806f, c0p = 1.0f;
        PACK2(P5, c5, c5); PACK2(P4, c4, c4); PACK2(P3, c3, c3);
        PACK2(P2, c2, c2); PACK2(P1c, c1p, c1p); PACK2(P0c, c0p, c0p);
    }

    for (int u = wgid; u < units; u += nwarps) {
        const int qw = u >> 4;                 // CHUNKS == 16
        const int c  = u & (CHUNKS - 1);
        const int q  = qw * 32 + lane;
        const bool act = (q < B);

        float xv = 0.0f, tv = 0.5f;
        if (act) { xv = x[q]; tv = t[q]; }

        const float sigma2 = sigma2_of(tv);
        const float k  = -0.5f * INV_LN2 / sigma2;
        const float c1 = -2.0f * k * xv;
        const float c0 = k * xv * xv;

        u64 KK, C1c, C0c, num2 = 0ULL, den2 = 0ULL;
        PACK2(KK, k, k);
        PACK2(C1c, c1, c1);
        PACK2(C0c, c0, c0);

        const float2* __restrict__ p = sp + c * PL;

        for (int ib = 0; ib < PL; ib += 16) {
            #pragma unroll
            for (int j = 0; j < 16; ++j) {
                float2 v = p[ib + j];
                if (j == 4 || j == 9 || j == 14)
                    pair_poly(v, KK, C1c, C0c, MG2,
                              P5, P4, P3, P2, P1c, P0c, num2, den2);
                else
                    pair_mufu(v, KK, C1c, C0c, num2, den2);
            }
        }

        float nlo, nhi, dlo, dhi;
        UNPACK2(nlo, nhi, num2);
        UNPACK2(dlo, dhi, den2);
        if (act)
            g_part[c * MAXB + q] = make_float2(nlo + nhi, dlo + dhi);
    }
}

__global__ void gmm_final_kernel(const float* __restrict__ x,
                                 const float* __restrict__ t,
                                 float* __restrict__ out,
                                 int B)
{
    __shared__ float2 red[RED_SUB][64];
    const int ql  = threadIdx.x & 63;
    const int sub = threadIdx.x >> 6;          // 0..3
    const int q   = blockIdx.x * 64 + ql;

    float num = 0.0f, den = 0.0f;
    if (q < B) {
        #pragma unroll
        for (int c = 0; c < CHUNKS / RED_SUB; ++c) {
            float2 pd = g_part[(sub * (CHUNKS / RED_SUB) + c) * MAXB + q];
            num += pd.x;
            den += pd.y;
        }
    }
    red[sub][ql] = make_float2(num, den);
    __syncthreads();

    if (sub == 0 && q < B) {
        #pragma unroll
        for (int s = 1; s < RED_SUB; ++s) {
            num += red[s][ql].x;
            den += red[s][ql].y;
        }
        float xv = x[q];
        float sigma2 = sigma2_of(t[q]);
        float evals = (den == 0.0f) ? 0.0f : (num / den);
        out[q] = (evals - xv) / sigma2;
    }
}

extern "C" void kernel_launch(void* const* d_in, const int* in_sizes, int n_in,
                              void* d_out, int out_size)
{
    const float* x     = (const float*)d_in[0];
    const float* t     = (const float*)d_in[1];
    const float* train = (const float*)d_in[2];
    float* out = (float*)d_out;

    int B = in_sizes[0];   // 16384
    int N = in_sizes[2];   // 16384

    int npairs = (N + 1) / 2;
    int PL = (npairs + CHUNKS - 1) / CHUNKS;
    PL = (PL + 15) & ~15;                                  // multiple of 16
    size_t smem = (size_t)CHUNKS * PL * sizeof(float2);    // 64 KB for N=16K

    static int sms = 0;
    if (!sms) {
        cudaDeviceGetAttribute(&sms, cudaDevAttrMultiProcessorCount, 0);
        if (sms <= 0) sms = 148;
        cudaFuncSetAttribute(gmm_partial_kernel,
                             cudaFuncAttributeMaxDynamicSharedMemorySize,
                             (int)smem);
    }

    gmm_partial_kernel<<<sms, TPB_A, smem>>>(x, t, train, B, N, PL);
    gmm_final_kernel<<<(B + 63) / 64, 256>>>(x, t, out, B);
}

// round 6
// speedup vs baseline: 1.1362x; 1.1362x over previous
#include <cuda_runtime.h>

// GMM score, d=1, single fused persistent kernel.
//   sigma2(t) = (exp(2 t ln25) - 1) / (2 ln25)
//   e_ij = 2^( (k*tr + c1)*tr + c0 ),  k = -1/(2 ln2 sigma2)
//   out[j] = (num/den - x[j]) / sigma2[j]   (den==0 guard as reference)
//
// Phase A: units of (query-warp x train-chunk), CHUNKS chosen so units divide
// the warp count exactly (perfect static balance). Pure-MUFU inner loop:
// per pair LDS(amortized .128) + 2 FFMA2 + 2 ex2 + FFMA2 + FADD2 -> MUFU
// binds at 16 cyc/pair/SMSP (113k cyc chip floor).
// Grid barrier (monotonic epoch counter; grid == SM count, 1 CTA/SM resident).
// Phase B in-kernel: each thread reduces CHUNKS partials for one query.

#define TPB       256
#define WPB       (TPB / 32)
#define MAXB      16384
#define CMAX      64

typedef unsigned long long u64;

__device__ float2 g_part[CMAX * MAXB];
__device__ unsigned int g_arrive = 0;

#define PACK2(d, lo, hi) \
    asm("mov.b64 %0, {%1, %2};" : "=l"(d) : "f"(lo), "f"(hi))
#define UNPACK2(lo, hi, s) \
    asm("mov.b64 {%0, %1}, %2;" : "=f"(lo), "=f"(hi) : "l"(s))
#define FMA2(d, a, b, c) \
    asm("fma.rn.f32x2 %0, %1, %2, %3;" : "=l"(d) : "l"(a), "l"(b), "l"(c))
#define ADD2(d, a, b) \
    asm("add.rn.f32x2 %0, %1, %2;" : "=l"(d) : "l"(a), "l"(b))
#define EX2(d, a) \
    asm("ex2.approx.ftz.f32 %0, %1;" : "=f"(d) : "f"(a))

__device__ __forceinline__ float sigma2_of(float tv) {
    const float LOG_S = 3.2188758248682006f;   // ln 25
    return (expf(2.0f * tv * LOG_S) - 1.0f) / (2.0f * LOG_S);
}

__device__ __forceinline__ void pair_mufu(u64 P, u64 KK, u64 C1c, u64 C0c,
                                          u64& num2, u64& den2)
{
    u64 t1, a2, E;
    FMA2(t1, KK, P, C1c);          // k*tr + c1
    FMA2(a2, t1, P, C0c);          // (k*tr + c1)*tr + c0
    float al, ah, e0, e1;
    UNPACK2(al, ah, a2);
    EX2(e0, al);
    EX2(e1, ah);
    PACK2(E, e0, e1);
    FMA2(num2, E, P, num2);
    ADD2(den2, den2, E);
}

__global__ __launch_bounds__(TPB, 1)
void gmm_fused_kernel(const float* __restrict__ x,
                      const float* __restrict__ t,
                      const float* __restrict__ train,
                      float* __restrict__ out,
                      int B, int N, int C /* chunks */, int PL /* pairs/chunk, even */)
{
    extern __shared__ u64 sp[];    // C*PL packed train pairs

    // ---- stage train, pre-packed as u64 pairs; pad with -1e30 (exp -> 0) ----
    const int tot = C * PL;
    for (int i = threadIdx.x; i < tot; i += TPB) {
        int e0 = 2 * i, e1 = 2 * i + 1;
        float a = (e0 < N) ? train[e0] : -1e30f;
        float b = (e1 < N) ? train[e1] : -1e30f;
        u64 pk;
        PACK2(pk, a, b);
        sp[i] = pk;
    }
    __syncthreads();

    const int lane   = threadIdx.x & 31;
    const int wid    = threadIdx.x >> 5;
    const int wgid   = blockIdx.x * WPB + wid;
    const int nwarps = gridDim.x * WPB;

    const int qwarps = (B + 31) >> 5;
    const int units  = qwarps * C;

    const float INV_LN2 = 1.4426950408889634f;

    // ---- phase A: per-unit partial sums ----
    for (int u = wgid; u < units; u += nwarps) {
        const int qw = u / C;
        const int c  = u - qw * C;
        const int q  = qw * 32 + lane;
        const bool act = (q < B);

        float xv = 0.0f, tv = 0.5f;
        if (act) { xv = x[q]; tv = t[q]; }

        const float sigma2 = sigma2_of(tv);
        const float k  = -0.5f * INV_LN2 / sigma2;
        const float c1 = -2.0f * k * xv;
        const float c0 = k * xv * xv;

        u64 KK, C1c, C0c, num2 = 0ULL, den2 = 0ULL;
        PACK2(KK, k, k);
        PACK2(C1c, c1, c1);
        PACK2(C0c, c0, c0);

        const ulonglong2* __restrict__ p =
            reinterpret_cast<const ulonglong2*>(sp + c * PL);
        const int iters = PL >> 1;             // 2 pairs per LDS.128

        #pragma unroll 4
        for (int i = 0; i < iters; ++i) {
            ulonglong2 v = p[i];               // broadcast LDS.128
            pair_mufu(v.x, KK, C1c, C0c, num2, den2);
            pair_mufu(v.y, KK, C1c, C0c, num2, den2);
        }

        float nlo, nhi, dlo, dhi;
        UNPACK2(nlo, nhi, num2);
        UNPACK2(dlo, dhi, den2);
        if (act)
            g_part[c * MAXB + q] = make_float2(nlo + nhi, dlo + dhi);
    }

    // ---- grid barrier (monotonic epoch; all CTAs resident by construction) ----
    __syncthreads();
    if (threadIdx.x == 0) {
        __threadfence();                                   // release partials
        unsigned old = atomicAdd(&g_arrive, 1u);
        unsigned target = (old / gridDim.x + 1u) * gridDim.x;
        while (*((volatile unsigned int*)&g_arrive) < target) { }
    }
    __syncthreads();
    __threadfence();                                       // acquire partials

    // ---- phase B: one thread per query reduces C partials + epilogue ----
    const int gq = blockIdx.x * TPB + threadIdx.x;
    if (gq < B) {
        float num = 0.0f, den = 0.0f;
        for (int c = 0; c < C; ++c) {                      // coalesced, L2-resident
            float2 pd = g_part[c * MAXB + gq];
            num += pd.x;
            den += pd.y;
        }
        float xv = x[gq];
        float sigma2 = sigma2_of(t[gq]);
        float evals = (den == 0.0f) ? 0.0f : (num / den);
        out[gq] = (evals - xv) / sigma2;
    }
}

static int gcd_i(int a, int b) { while (b) { int r = a % b; a = b; b = r; } return a; }

extern "C" void kernel_launch(void* const* d_in, const int* in_sizes, int n_in,
                              void* d_out, int out_size)
{
    const float* x     = (const float*)d_in[0];
    const float* t     = (const float*)d_in[1];
    const float* train = (const float*)d_in[2];
    float* out = (float*)d_out;

    int B = in_sizes[0];   // 16384
    int N = in_sizes[2];   // 16384

    static int sms = 0;
    static int C = 0, PL = 0;
    static size_t smem = 0;
    if (!sms) {
        cudaDeviceGetAttribute(&sms, cudaDevAttrMultiProcessorCount, 0);
        if (sms <= 0) sms = 148;

        int warps  = sms * WPB;
        int qwarps = (B + 31) / 32;
        // choose C so qwarps*C is an exact multiple of warps (perfect balance)
        C = warps / gcd_i(qwarps, warps);
        if (C < 8)  C *= (8 / C + (8 % C ? 1 : 0));        // enough chunks for phase B split
        if (C > CMAX) C = 16;                               // fallback
        int npairs = (N + 1) / 2;
        PL = (npairs + C - 1) / C;
        PL = (PL + 1) & ~1;                                 // even (LDS.128)
        smem = (size_t)C * PL * sizeof(u64);
        cudaFuncSetAttribute(gmm_fused_kernel,
                             cudaFuncAttributeMaxDynamicSharedMemorySize,
                             (int)smem);
    }

    gmm_fused_kernel<<<sms, TPB, smem>>>(x, t, train, out, B, N, C, PL);
}

// round 8
// speedup vs baseline: 1.1784x; 1.0371x over previous
#include <cuda_runtime.h>

// GMM score, d=1, fused persistent kernel, hybrid MUFU/FMA exponential.
//   sigma2(t) = (exp(2 t ln25) - 1) / (2 ln25)
//   e_ij = 2^( (k*tr + c1)*tr + c0 ),  k = -1/(2 ln2 sigma2)
//   out[j] = (num/den - x[j]) / sigma2[j]   (den==0 guard as reference)
//
// Phase A: units (query-warp x train-chunk), C chosen so units divide warp
// count exactly. 7 of 8 pairs via MUFU ex2; 1 of 8 via lean packed FMA-pipe
// exp2 (magic round, IMAD scale, deg-4 f32x2 Horner, FMNMX clamp on ALU).
// MUFU 14 cyc/pair vs FMA ~10.5-14.4 -> ~12% under the pure-MUFU floor.
// Grid barrier (monotonic epoch, grid == SM count, 1 CTA/SM).
// Phase B in-kernel: thread-per-query reduction of C partials + epilogue.

#define TPB       512
#define WPB       (TPB / 32)
#define MAXB      16384
#define CMAX      64

typedef unsigned long long u64;

__device__ float2 g_part[CMAX * MAXB];
__device__ unsigned int g_arrive = 0;

#define PACK2(d, lo, hi) \
    asm("mov.b64 %0, {%1, %2};" : "=l"(d) : "f"(lo), "f"(hi))
#define UNPACK2(lo, hi, s) \
    asm("mov.b64 {%0, %1}, %2;" : "=f"(lo), "=f"(hi) : "l"(s))
#define FMA2(d, a, b, c) \
    asm("fma.rn.f32x2 %0, %1, %2, %3;" : "=l"(d) : "l"(a), "l"(b), "l"(c))
#define ADD2(d, a, b) \
    asm("add.rn.f32x2 %0, %1, %2;" : "=l"(d) : "l"(a), "l"(b))
#define MUL2(d, a, b) \
    asm("mul.rn.f32x2 %0, %1, %2;" : "=l"(d) : "l"(a), "l"(b))
#define EX2(d, a) \
    asm("ex2.approx.ftz.f32 %0, %1;" : "=f"(d) : "f"(a))

struct PolyC {
    u64 MG2, MG2N, NEG1, PC4, PC3, PC2, PC1, PC0;
};

__device__ __forceinline__ float sigma2_of(float tv) {
    const float LOG_S = 3.2188758248682006f;   // ln 25
    return (expf(2.0f * tv * LOG_S) - 1.0f) / (2.0f * LOG_S);
}

// MUFU path: 4 packed FMA ops + 2 MUFU ex2 per pair
__device__ __forceinline__ void pair_mufu(u64 P, u64 KK, u64 C1c, u64 C0c,
                                          u64& num2, u64& den2)
{
    u64 t1, a2, E;
    FMA2(t1, KK, P, C1c);
    FMA2(a2, t1, P, C0c);
    float al, ah, e0, e1;
    UNPACK2(al, ah, a2);
    EX2(e0, al);
    EX2(e1, ah);
    PACK2(E, e0, e1);
    FMA2(num2, E, P, num2);
    ADD2(den2, den2, E);
}

// FMA-pipe path: 12 packed ops + 2 IMAD (+2 FMNMX on ALU) per pair
__device__ __forceinline__ void pair_poly(u64 P, u64 KK, u64 C1c, u64 C0c,
                                          const PolyC& pc,
                                          u64& num2, u64& den2)
{
    u64 t1, a2;
    FMA2(t1, KK, P, C1c);
    FMA2(a2, t1, P, C0c);
    float a0, a1;
    UNPACK2(a0, a1, a2);
    a0 = fmaxf(a0, -126.0f);                  // FMNMX (alu pipe)
    a1 = fmaxf(a1, -126.0f);
    u64 ac; PACK2(ac, a0, a1);
    u64 r2; ADD2(r2, ac, pc.MG2);             // r = a + MAGIC (round-to-nearest int)
    u64 n2; ADD2(n2, r2, pc.MG2N);            // n = r - MAGIC (exact)
    u64 f2; FMA2(f2, n2, pc.NEG1, ac);        // f = a - n, f in [-0.5, 0.5]
    float r0, r1;
    UNPACK2(r0, r1, r2);
    unsigned s0 = __float_as_uint(r0) * 0x800000u + 0x3F800000u;  // 2^n bits
    unsigned s1 = __float_as_uint(r1) * 0x800000u + 0x3F800000u;
    u64 pp;
    FMA2(pp, pc.PC4, f2, pc.PC3);             // deg-4 Horner for 2^f
    FMA2(pp, pp, f2, pc.PC2);
    FMA2(pp, pp, f2, pc.PC1);
    FMA2(pp, pp, f2, pc.PC0);
    u64 S; PACK2(S, __uint_as_float(s0), __uint_as_float(s1));
    u64 E; MUL2(E, pp, S);
    FMA2(num2, E, P, num2);
    ADD2(den2, den2, E);
}

__global__ __launch_bounds__(TPB, 1)
void gmm_fused_kernel(const float* __restrict__ x,
                      const float* __restrict__ t,
                      const float* __restrict__ train,
                      float* __restrict__ out,
                      int B, int N, int C, int PL /* pairs/chunk, even */)
{
    extern __shared__ u64 sp[];    // C*PL packed train pairs

    // Stage train pre-packed; pad -6e17: finite exponent chain, e==0 (mufu)
    // or ~1.2e-38 (poly, clamped) -> negligible.
    const int tot = C * PL;
    for (int i = threadIdx.x; i < tot; i += TPB) {
        int e0 = 2 * i, e1 = 2 * i + 1;
        float a = (e0 < N) ? train[e0] : -6e17f;
        float b = (e1 < N) ? train[e1] : -6e17f;
        u64 pk;
        PACK2(pk, a, b);
        sp[i] = pk;
    }
    __syncthreads();

    const int lane   = threadIdx.x & 31;
    const int wid    = threadIdx.x >> 5;
    const int wgid   = blockIdx.x * WPB + wid;
    const int nwarps = gridDim.x * WPB;

    const int qwarps = (B + 31) >> 5;
    const int units  = qwarps * C;

    const float INV_LN2 = 1.4426950408889634f;
    const float MAGIC   = 12582912.0f;         // 1.5 * 2^23

    PolyC pc;
    PACK2(pc.MG2,  MAGIC,  MAGIC);
    PACK2(pc.MG2N, -MAGIC, -MAGIC);
    PACK2(pc.NEG1, -1.0f, -1.0f);
    {
        const float c4 = 0.0096181291f, c3 = 0.0555041087f,
                    c2 = 0.2402265070f, c1p = 0.6931471806f, c0p = 1.0f;
        PACK2(pc.PC4, c4, c4); PACK2(pc.PC3, c3, c3); PACK2(pc.PC2, c2, c2);
        PACK2(pc.PC1, c1p, c1p); PACK2(pc.PC0, c0p, c0p);
    }

    // ---- phase A ----
    for (int u = wgid; u < units; u += nwarps) {
        const int qw = u / C;
        const int c  = u - qw * C;
        const int q  = qw * 32 + lane;
        const bool act = (q < B);

        float xv = 0.0f, tv = 0.5f;
        if (act) { xv = x[q]; tv = t[q]; }

        const float sigma2 = sigma2_of(tv);
        const float k  = -0.5f * INV_LN2 / sigma2;
        const float c1 = -2.0f * k * xv;
        const float c0 = k * xv * xv;

        u64 KK, C1c, C0c, num2 = 0ULL, den2 = 0ULL;
        PACK2(KK, k, k);
        PACK2(C1c, c1, c1);
        PACK2(C0c, c0, c0);

        const ulonglong2* __restrict__ p =
            reinterpret_cast<const ulonglong2*>(sp + c * PL);
        const int iters  = PL >> 1;            // 2 pairs per LDS.128
        const int blocks = iters >> 2;         // 8 pairs per block

        int i = 0;
        for (int b = 0; b < blocks; ++b, i += 4) {
            ulonglong2 v0 = p[i + 0];
            ulonglong2 v1 = p[i + 1];
            ulonglong2 v2 = p[i + 2];
            ulonglong2 v3 = p[i + 3];
            pair_mufu(v0.x, KK, C1c, C0c, num2, den2);
            pair_mufu(v0.y, KK, C1c, C0c, num2, den2);
            pair_mufu(v1.x, KK, C1c, C0c, num2, den2);
            pair_poly(v1.y, KK, C1c, C0c, pc, num2, den2);   // 1 of 8
            pair_mufu(v2.x, KK, C1c, C0c, num2, den2);
            pair_mufu(v2.y, KK, C1c, C0c, num2, den2);
            pair_mufu(v3.x, KK, C1c, C0c, num2, den2);
            pair_mufu(v3.y, KK, C1c, C0c, num2, den2);
        }
        for (; i < iters; ++i) {               // tail (PL%8 != 0)
            ulonglong2 v = p[i];
            pair_mufu(v.x, KK, C1c, C0c, num2, den2);
            pair_mufu(v.y, KK, C1c, C0c, num2, den2);
        }

        float nlo, nhi, dlo, dhi;
        UNPACK2(nlo, nhi, num2);
        UNPACK2(dlo, dhi, den2);
        if (act)
            g_part[c * MAXB + q] = make_float2(nlo + nhi, dlo + dhi);
    }

    // ---- grid barrier (monotonic epoch; grid == SM count, all resident) ----
    __syncthreads();
    if (threadIdx.x == 0) {
        __threadfence();
        unsigned old = atomicAdd(&g_arrive, 1u);
        unsigned target = (old / gridDim.x + 1u) * gridDim.x;
        while (*((volatile unsigned int*)&g_arrive) < target) { }
    }
    __syncthreads();
    __threadfence();

    // ---- phase B ----
    const int gq = blockIdx.x * TPB + threadIdx.x;
    if (gq < B) {
        float num = 0.0f, den = 0.0f;
        for (int c = 0; c < C; ++c) {
            float2 pd = g_part[c * MAXB + gq];
            num += pd.x;
            den += pd.y;
        }
        float xv = x[gq];
        float sigma2 = sigma2_of(t[gq]);
        float evals = (den == 0.0f) ? 0.0f : (num / den);
        out[gq] = (evals - xv) / sigma2;
    }
}

static int gcd_i(int a, int b) { while (b) { int r = a % b; a = b; b = r; } return a; }

extern "C" void kernel_launch(void* const* d_in, const int* in_sizes, int n_in,
                              void* d_out, int out_size)
{
    const float* x     = (const float*)d_in[0];
    const float* t     = (const float*)d_in[1];
    const float* train = (const float*)d_in[2];
    float* out = (float*)d_out;

    int B = in_sizes[0];   // 16384
    int N = in_sizes[2];   // 16384

    static int sms = 0;
    static int C = 0, PL = 0;
    static size_t smem = 0;
    if (!sms) {
        cudaDeviceGetAttribute(&sms, cudaDevAttrMultiProcessorCount, 0);
        if (sms <= 0) sms = 148;

        int warps  = sms * WPB;
        int qwarps = (B + 31) / 32;
        C = warps / gcd_i(qwarps, warps);          // exact static balance
        if (C < 8)  C *= (8 / C + (8 % C ? 1 : 0));
        if (C > CMAX) C = 16;                      // fallback
        int npairs = (N + 1) / 2;
        PL = (npairs + C - 1) / C;
        PL = (PL + 1) & ~1;                        // even (LDS.128)
        smem = (size_t)C * PL * sizeof(u64);
        cudaFuncSetAttribute(gmm_fused_kernel,
                             cudaFuncAttributeMaxDynamicSharedMemorySize,
                             (int)smem);
    }

    gmm_fused_kernel<<<sms, TPB, smem>>>(x, t, train, out, B, N, C, PL);
}